// round 9
// baseline (speedup 1.0000x reference)
#include <cuda_runtime.h>
#include <cstdint>

#define T_STEPS 256
#define HH 512
#define WW 512
#define TILE 32
#define SMROWS 36           // tile + 2*2 halo rows
#define SMSTRIDE 40         // floats per staged row: cols [gx0-4, gx0+36)
#define NCHUNK 10           // float4 chunks per row
#define CHUNKS (SMROWS * NCHUNK)   // 360
#define STAGE_ELEMS (SMROWS * SMSTRIDE)
#define NTHREADS 128

#define ALPHA_LIF 0.85f
#define V_TH      2.0f
#define ALPHA_LI  0.9f

typedef unsigned long long u64;

// ---- packed f32x2 helpers ----
__device__ __forceinline__ u64 pk(float lo, float hi) {
    u64 r; asm("mov.b64 %0, {%1, %2};" : "=l"(r) : "f"(lo), "f"(hi)); return r;
}
__device__ __forceinline__ void upk(u64 p, float& lo, float& hi) {
    asm("mov.b64 {%0, %1}, %2;" : "=f"(lo), "=f"(hi) : "l"(p));
}
__device__ __forceinline__ void ffma2(u64& acc, u64 a, u64 b) {
    asm("fma.rn.f32x2 %0, %1, %2, %0;" : "+l"(acc) : "l"(a), "l"(b));
}
__device__ __forceinline__ u64 ffma2g(u64 a, u64 b, u64 c) {
    u64 d; asm("fma.rn.f32x2 %0, %1, %2, %3;" : "=l"(d) : "l"(a), "l"(b), "l"(c)); return d;
}
// (hi(a), lo(b)) as a packed pair — extract movs are register renames;
// only the final pack can cost real MOVs.
__device__ __forceinline__ u64 pair_hl(u64 a, u64 b) {
    u64 r;
    asm("{\n\t"
        ".reg .b32 al, ah, bl, bh;\n\t"
        "mov.b64 {al, ah}, %1;\n\t"
        "mov.b64 {bl, bh}, %2;\n\t"
        "mov.b64 %0, {ah, bl};\n\t"
        "}" : "=l"(r) : "l"(a), "l"(b));
    return r;
}

// ---- cp.async helpers ----
__device__ __forceinline__ void cp_async16(float* smem_dst, const float* gsrc, bool pred) {
    uint32_t s = (uint32_t)__cvta_generic_to_shared(smem_dst);
    int srcsz = pred ? 16 : 0;
    asm volatile("cp.async.cg.shared.global [%0], [%1], 16, %2;\n"
                 :: "r"(s), "l"(gsrc), "r"(srcsz));
}
__device__ __forceinline__ void cp_async_commit() {
    asm volatile("cp.async.commit_group;\n" ::: "memory");
}
__device__ __forceinline__ void cp_async_wait1() {
    asm volatile("cp.async.wait_group 1;\n" ::: "memory");
}

__global__ __launch_bounds__(NTHREADS, 2)
void snn_fused_kernel(const float* __restrict__ x,
                      const float* __restrict__ kw,
                      float* __restrict__ out) {
    __shared__ float sm[3][STAGE_ELEMS];

    const int tid = threadIdx.x;
    const int tx  = tid & 7;      // 0..7  -> 4 px each => 32 px wide
    const int ty2 = tid >> 3;     // 0..15 -> 2 rows each => 32 rows
    const int yA  = ty2 * 2;      // first output row within tile
    const int gx0 = blockIdx.x * TILE;
    const int gy0 = blockIdx.y * TILE;

    // conv weights -> packed (w,w) pairs
    u64 W2[25];
#pragma unroll
    for (int i = 0; i < 25; i++) { float wv = __ldg(&kw[i]); W2[i] = pk(wv, wv); }

    const u64 ALIF2 = pk(ALPHA_LIF, ALPHA_LIF);
    const u64 NTH2  = pk(-V_TH, -V_TH);
    const u64 ALI2  = pk(ALPHA_LI, ALPHA_LI);
    const u64 ZERO2 = pk(0.f, 0.f);

    // Vector staging map: 360 float4 chunks, <=3 per thread (128 threads).
    int  goff[3];
    int  sdst[3];
    bool gok[3];
    bool act[3];
#pragma unroll
    for (int j = 0; j < 3; j++) {
        int i = tid + j * NTHREADS;
        act[j] = (i < CHUNKS);
        int r = i / NCHUNK;
        int k = i - r * NCHUNK;
        int gy  = gy0 - 2 + r;
        int gxc = gx0 - 4 + 4 * k;
        bool ok = act[j] && ((unsigned)gy < (unsigned)HH)
                         && (gxc >= 0) && (gxc <= WW - 4);
        gok[j]  = ok;
        goff[j] = ok ? (gy * WW + gxc) : 0;
        sdst[j] = r * SMSTRIDE + 4 * k;
    }

    // ---- prologue: stage t=0 and t=1 ----
#pragma unroll
    for (int j = 0; j < 3; j++)
        if (act[j]) cp_async16(&sm[0][sdst[j]], &x[goff[j]], gok[j]);
    cp_async_commit();
#pragma unroll
    for (int j = 0; j < 3; j++)
        if (act[j]) cp_async16(&sm[1][sdst[j]], &x[goff[j] + HH * WW], gok[j]);
    cp_async_commit();

    // packed per-pixel LIF / LI state for 2 rows x 4 cols
    u64 S1A0 = ZERO2, S1A1 = ZERO2, S1B0 = ZERO2, S1B1 = ZERO2;
    u64 S2A0 = ZERO2, S2A1 = ZERO2, S2B0 = ZERO2, S2B1 = ZERO2;

    const int orow = (gy0 + yA) * WW + gx0 + tx * 4;
    float* ot = out + orow;
    const float* xfut = x + 2 * HH * WW;

    int cur = 0;

    for (int t = 0; t < T_STEPS; t++) {
        cp_async_wait1();
        __syncthreads();

        // stage t+2
        int nxt2 = cur + 2; if (nxt2 >= 3) nxt2 -= 3;
        if (t + 2 < T_STEPS) {
#pragma unroll
            for (int j = 0; j < 3; j++)
                if (act[j]) cp_async16(&sm[nxt2][sdst[j]], &xfut[goff[j]], gok[j]);
        }
        cp_async_commit();

        // 5x5 conv for 2 output rows x 4 cols.
        // Loaded smem row (yA + r), r = 0..5. Taps f0..f7 = cols tx*4+2 .. tx*4+9.
        // LDS.128 as ulonglong2: each .x/.y is already a packed f32x2 operand.
        u64 Aa0 = ZERO2, Aa1 = ZERO2;   // output row A, col-pairs (0,1) and (2,3)
        u64 Ab0 = ZERO2, Ab1 = ZERO2;   // output row B
#pragma unroll
        for (int r = 0; r < 6; r++) {
            const float* rp = &sm[cur][(yA + r) * SMSTRIDE + tx * 4];
            ulonglong2 La = *(const ulonglong2*)rp;        // (q0,q1),(q2,q3)=(f0,f1)
            ulonglong2 Lm = *(const ulonglong2*)(rp + 4);  // (f2,f3),(f4,f5)
            ulonglong2 Lb = *(const ulonglong2*)(rp + 8);  // (f6,f7),(f8,f9)

            u64 AP0 = La.y;             // (f0,f1)  zero-cost
            u64 AP1 = Lm.x;             // (f2,f3)
            u64 AP2 = Lm.y;             // (f4,f5)
            u64 AP3 = Lb.x;             // (f6,f7)
            u64 P12 = pair_hl(La.y, Lm.x);   // (f1,f2)
            u64 P34 = pair_hl(Lm.x, Lm.y);   // (f3,f4)
            u64 P56 = pair_hl(Lm.y, Lb.x);   // (f5,f6)

            if (r < 5) {        // contributes to row A with weight row r
                ffma2(Aa0, W2[r*5+0], AP0);
                ffma2(Aa0, W2[r*5+1], P12);
                ffma2(Aa0, W2[r*5+2], AP1);
                ffma2(Aa0, W2[r*5+3], P34);
                ffma2(Aa0, W2[r*5+4], AP2);

                ffma2(Aa1, W2[r*5+0], AP1);
                ffma2(Aa1, W2[r*5+1], P34);
                ffma2(Aa1, W2[r*5+2], AP2);
                ffma2(Aa1, W2[r*5+3], P56);
                ffma2(Aa1, W2[r*5+4], AP3);
            }
            if (r >= 1) {       // contributes to row B with weight row r-1
                int q = (r - 1) * 5;
                ffma2(Ab0, W2[q+0], AP0);
                ffma2(Ab0, W2[q+1], P12);
                ffma2(Ab0, W2[q+2], AP1);
                ffma2(Ab0, W2[q+3], P34);
                ffma2(Ab0, W2[q+4], AP2);

                ffma2(Ab1, W2[q+0], AP1);
                ffma2(Ab1, W2[q+1], P34);
                ffma2(Ab1, W2[q+2], AP2);
                ffma2(Ab1, W2[q+3], P56);
                ffma2(Ab1, W2[q+4], AP3);
            }
        }

        // FastLIF (soft reset) + FastLI, packed — row A
        {
            u64 V0 = ffma2g(ALIF2, S1A0, Aa0);
            u64 V1 = ffma2g(ALIF2, S1A1, Aa1);
            float v0, v1, v2, v3;
            upk(V0, v0, v1);
            upk(V1, v2, v3);
            float k0 = (v0 >= V_TH) ? 1.0f : 0.0f;
            float k1 = (v1 >= V_TH) ? 1.0f : 0.0f;
            float k2 = (v2 >= V_TH) ? 1.0f : 0.0f;
            float k3 = (v3 >= V_TH) ? 1.0f : 0.0f;
            u64 K0 = pk(k0, k1);
            u64 K1 = pk(k2, k3);
            S1A0 = ffma2g(K0, NTH2, V0);
            S1A1 = ffma2g(K1, NTH2, V1);
            S2A0 = ffma2g(ALI2, S2A0, K0);
            S2A1 = ffma2g(ALI2, S2A1, K1);
            float4 o;
            upk(S2A0, o.x, o.y);
            upk(S2A1, o.z, o.w);
            *(float4*)ot = o;
        }
        // row B
        {
            u64 V0 = ffma2g(ALIF2, S1B0, Ab0);
            u64 V1 = ffma2g(ALIF2, S1B1, Ab1);
            float v0, v1, v2, v3;
            upk(V0, v0, v1);
            upk(V1, v2, v3);
            float k0 = (v0 >= V_TH) ? 1.0f : 0.0f;
            float k1 = (v1 >= V_TH) ? 1.0f : 0.0f;
            float k2 = (v2 >= V_TH) ? 1.0f : 0.0f;
            float k3 = (v3 >= V_TH) ? 1.0f : 0.0f;
            u64 K0 = pk(k0, k1);
            u64 K1 = pk(k2, k3);
            S1B0 = ffma2g(K0, NTH2, V0);
            S1B1 = ffma2g(K1, NTH2, V1);
            S2B0 = ffma2g(ALI2, S2B0, K0);
            S2B1 = ffma2g(ALI2, S2B1, K1);
            float4 o;
            upk(S2B0, o.x, o.y);
            upk(S2B1, o.z, o.w);
            *(float4*)(ot + WW) = o;
        }

        cur = cur + 1; if (cur >= 3) cur -= 3;
        xfut += HH * WW;
        ot   += HH * WW;
    }
}

extern "C" void kernel_launch(void* const* d_in, const int* in_sizes, int n_in,
                              void* d_out, int out_size) {
    const float* x  = (const float*)d_in[0];   // [256,1,512,512] f32
    const float* kw = (const float*)d_in[1];   // [1,1,5,5] f32
    float* out = (float*)d_out;                // [256,1,512,512] f32
    (void)in_sizes; (void)n_in; (void)out_size;

    dim3 grid(WW / TILE, HH / TILE);           // 16 x 16 tiles
    dim3 block(NTHREADS);
    snn_fused_kernel<<<grid, block>>>(x, kw, out);
}

// round 12
// speedup vs baseline: 1.0963x; 1.0963x over previous
#include <cuda_runtime.h>
#include <cstdint>

#define T_STEPS 256
#define HH 512
#define WW 512
#define TILE_W 32
#define TILE_H 8
#define SMROWS 12           // TILE_H + 2*2 halo rows
#define SMSTRIDE 40         // floats per staged row: cols [gx0-4, gx0+36)
#define NCHUNK 10           // float4 chunks per row
#define CHUNKS (SMROWS * NCHUNK)   // 120
#define STAGE_ELEMS (SMROWS * SMSTRIDE)
#define NTHREADS 32

#define ALPHA_LIF 0.85f
#define V_TH      2.0f
#define ALPHA_LI  0.9f

typedef unsigned long long u64;

// ---- packed f32x2 helpers ----
__device__ __forceinline__ u64 pk(float lo, float hi) {
    u64 r; asm("mov.b64 %0, {%1, %2};" : "=l"(r) : "f"(lo), "f"(hi)); return r;
}
__device__ __forceinline__ void upk(u64 p, float& lo, float& hi) {
    asm("mov.b64 {%0, %1}, %2;" : "=f"(lo), "=f"(hi) : "l"(p));
}
__device__ __forceinline__ void ffma2(u64& acc, u64 a, u64 b) {
    asm("fma.rn.f32x2 %0, %1, %2, %0;" : "+l"(acc) : "l"(a), "l"(b));
}
__device__ __forceinline__ u64 ffma2g(u64 a, u64 b, u64 c) {
    u64 d; asm("fma.rn.f32x2 %0, %1, %2, %3;" : "=l"(d) : "l"(a), "l"(b), "l"(c)); return d;
}

// ---- cp.async helpers ----
__device__ __forceinline__ void cp_async16(float* smem_dst, const float* gsrc, bool pred) {
    uint32_t s = (uint32_t)__cvta_generic_to_shared(smem_dst);
    int srcsz = pred ? 16 : 0;
    asm volatile("cp.async.cg.shared.global [%0], [%1], 16, %2;\n"
                 :: "r"(s), "l"(gsrc), "r"(srcsz));
}
__device__ __forceinline__ void cp_async_commit() {
    asm volatile("cp.async.commit_group;\n" ::: "memory");
}
__device__ __forceinline__ void cp_async_wait1() {
    asm volatile("cp.async.wait_group 1;\n" ::: "memory");
}

__global__ __launch_bounds__(NTHREADS)
void snn_fused_kernel(const float* __restrict__ x,
                      const float* __restrict__ kw,
                      float* __restrict__ out) {
    __shared__ float sm[3][STAGE_ELEMS];

    const int tid = threadIdx.x;          // 0..31 (one warp per CTA)
    const int tx  = tid & 7;              // 0..7  -> 4 px each => 32 px wide
    const int ty2 = tid >> 3;             // 0..3  -> 2 rows each => 8 rows
    const int yA  = ty2 * 2;              // first output row within tile
    const int gx0 = blockIdx.x * TILE_W;
    const int gy0 = blockIdx.y * TILE_H;

    // conv weights -> packed (w,w) pairs
    u64 W2[25];
#pragma unroll
    for (int i = 0; i < 25; i++) { float wv = __ldg(&kw[i]); W2[i] = pk(wv, wv); }

    const u64 ALIF2 = pk(ALPHA_LIF, ALPHA_LIF);
    const u64 NTH2  = pk(-V_TH, -V_TH);
    const u64 ALI2  = pk(ALPHA_LI, ALPHA_LI);
    const u64 ZERO2 = pk(0.f, 0.f);

    // Vector staging map: 120 float4 chunks, <=4 per thread (32 threads).
    int  goff[4];
    int  sdst[4];
    bool gok[4];
    bool act[4];
#pragma unroll
    for (int j = 0; j < 4; j++) {
        int i = tid + j * NTHREADS;
        act[j] = (i < CHUNKS);
        int r = i / NCHUNK;
        int k = i - r * NCHUNK;
        int gy  = gy0 - 2 + r;
        int gxc = gx0 - 4 + 4 * k;
        bool ok = act[j] && ((unsigned)gy < (unsigned)HH)
                         && (gxc >= 0) && (gxc <= WW - 4);
        gok[j]  = ok;
        goff[j] = ok ? (gy * WW + gxc) : 0;
        sdst[j] = r * SMSTRIDE + 4 * k;
    }

    // ---- prologue: stage t=0 and t=1 ----
#pragma unroll
    for (int j = 0; j < 4; j++)
        if (act[j]) cp_async16(&sm[0][sdst[j]], &x[goff[j]], gok[j]);
    cp_async_commit();
#pragma unroll
    for (int j = 0; j < 4; j++)
        if (act[j]) cp_async16(&sm[1][sdst[j]], &x[goff[j] + HH * WW], gok[j]);
    cp_async_commit();

    // packed per-pixel LIF / LI state for 2 rows x 4 cols
    u64 S1A0 = ZERO2, S1A1 = ZERO2, S1B0 = ZERO2, S1B1 = ZERO2;
    u64 S2A0 = ZERO2, S2A1 = ZERO2, S2B0 = ZERO2, S2B1 = ZERO2;

    const int orow = (gy0 + yA) * WW + gx0 + tx * 4;
    float* ot = out + orow;
    const float* xfut = x + 2 * HH * WW;

    int cur = 0;

    for (int t = 0; t < T_STEPS; t++) {
        // everything is warp-local: cp.async groups + smem visibility
        cp_async_wait1();
        __syncwarp();

        // stage t+2
        int nxt2 = cur + 2; if (nxt2 >= 3) nxt2 -= 3;
        if (t + 2 < T_STEPS) {
#pragma unroll
            for (int j = 0; j < 4; j++)
                if (act[j]) cp_async16(&sm[nxt2][sdst[j]], &xfut[goff[j]], gok[j]);
        }
        cp_async_commit();

        // 5x5 conv for 2 output rows x 4 cols.
        // Loaded smem row (yA + r), r = 0..5. Taps f0..f7 = cols tx*4+2 .. tx*4+9.
        // Conv reads are conflict-free LDS.128 (quarter-warp = single row).
        u64 Aa0 = ZERO2, Aa1 = ZERO2;   // output row A, col-pairs (0,1) and (2,3)
        u64 Ab0 = ZERO2, Ab1 = ZERO2;   // output row B
#pragma unroll
        for (int r = 0; r < 6; r++) {
            const float* rp = &sm[cur][(yA + r) * SMSTRIDE + tx * 4];
            float4 qa = *(const float4*)rp;        // q0..q3 (f-2..f1)
            float4 qm = *(const float4*)(rp + 4);  // f2..f5
            float4 qb = *(const float4*)(rp + 8);  // f6..f9

            u64 AP0 = pk(qa.z, qa.w);   // (f0,f1)
            u64 AP1 = pk(qm.x, qm.y);   // (f2,f3)
            u64 AP2 = pk(qm.z, qm.w);   // (f4,f5)
            u64 AP3 = pk(qb.x, qb.y);   // (f6,f7)
            u64 P12 = pk(qa.w, qm.x);   // (f1,f2)
            u64 P34 = pk(qm.y, qm.z);   // (f3,f4)
            u64 P56 = pk(qm.w, qb.x);   // (f5,f6)

            if (r < 5) {        // contributes to row A with weight row r
                ffma2(Aa0, W2[r*5+0], AP0);
                ffma2(Aa0, W2[r*5+1], P12);
                ffma2(Aa0, W2[r*5+2], AP1);
                ffma2(Aa0, W2[r*5+3], P34);
                ffma2(Aa0, W2[r*5+4], AP2);

                ffma2(Aa1, W2[r*5+0], AP1);
                ffma2(Aa1, W2[r*5+1], P34);
                ffma2(Aa1, W2[r*5+2], AP2);
                ffma2(Aa1, W2[r*5+3], P56);
                ffma2(Aa1, W2[r*5+4], AP3);
            }
            if (r >= 1) {       // contributes to row B with weight row r-1
                int q = (r - 1) * 5;
                ffma2(Ab0, W2[q+0], AP0);
                ffma2(Ab0, W2[q+1], P12);
                ffma2(Ab0, W2[q+2], AP1);
                ffma2(Ab0, W2[q+3], P34);
                ffma2(Ab0, W2[q+4], AP2);

                ffma2(Ab1, W2[q+0], AP1);
                ffma2(Ab1, W2[q+1], P34);
                ffma2(Ab1, W2[q+2], AP2);
                ffma2(Ab1, W2[q+3], P56);
                ffma2(Ab1, W2[q+4], AP3);
            }
        }

        // FastLIF (soft reset) + FastLI, packed — row A
        {
            u64 V0 = ffma2g(ALIF2, S1A0, Aa0);
            u64 V1 = ffma2g(ALIF2, S1A1, Aa1);
            float v0, v1, v2, v3;
            upk(V0, v0, v1);
            upk(V1, v2, v3);
            float k0 = (v0 >= V_TH) ? 1.0f : 0.0f;
            float k1 = (v1 >= V_TH) ? 1.0f : 0.0f;
            float k2 = (v2 >= V_TH) ? 1.0f : 0.0f;
            float k3 = (v3 >= V_TH) ? 1.0f : 0.0f;
            u64 K0 = pk(k0, k1);
            u64 K1 = pk(k2, k3);
            S1A0 = ffma2g(K0, NTH2, V0);
            S1A1 = ffma2g(K1, NTH2, V1);
            S2A0 = ffma2g(ALI2, S2A0, K0);
            S2A1 = ffma2g(ALI2, S2A1, K1);
            float4 o;
            upk(S2A0, o.x, o.y);
            upk(S2A1, o.z, o.w);
            *(float4*)ot = o;
        }
        // row B
        {
            u64 V0 = ffma2g(ALIF2, S1B0, Ab0);
            u64 V1 = ffma2g(ALIF2, S1B1, Ab1);
            float v0, v1, v2, v3;
            upk(V0, v0, v1);
            upk(V1, v2, v3);
            float k0 = (v0 >= V_TH) ? 1.0f : 0.0f;
            float k1 = (v1 >= V_TH) ? 1.0f : 0.0f;
            float k2 = (v2 >= V_TH) ? 1.0f : 0.0f;
            float k3 = (v3 >= V_TH) ? 1.0f : 0.0f;
            u64 K0 = pk(k0, k1);
            u64 K1 = pk(k2, k3);
            S1B0 = ffma2g(K0, NTH2, V0);
            S1B1 = ffma2g(K1, NTH2, V1);
            S2B0 = ffma2g(ALI2, S2B0, K0);
            S2B1 = ffma2g(ALI2, S2B1, K1);
            float4 o;
            upk(S2B0, o.x, o.y);
            upk(S2B1, o.z, o.w);
            *(float4*)(ot + WW) = o;
        }

        cur = cur + 1; if (cur >= 3) cur -= 3;
        xfut += HH * WW;
        ot   += HH * WW;
    }
}

extern "C" void kernel_launch(void* const* d_in, const int* in_sizes, int n_in,
                              void* d_out, int out_size) {
    const float* x  = (const float*)d_in[0];   // [256,1,512,512] f32
    const float* kw = (const float*)d_in[1];   // [1,1,5,5] f32
    float* out = (float*)d_out;                // [256,1,512,512] f32
    (void)in_sizes; (void)n_in; (void)out_size;

    dim3 grid(WW / TILE_W, HH / TILE_H);       // 16 x 64 = 1024 warp-sized CTAs
    dim3 block(NTHREADS);
    snn_fused_kernel<<<grid, block>>>(x, kw, out);
}

// round 15
// speedup vs baseline: 1.1072x; 1.0099x over previous
#include <cuda_runtime.h>
#include <cstdint>

#define T_STEPS 256
#define HH 512
#define WW 512
#define TILE_W 32
#define TILE_H 8
#define SMROWS 12           // TILE_H + 2*2 halo rows
#define SMSTRIDE 40         // floats per staged row: cols [gx0-4, gx0+36)
#define NCHUNK 10           // float4 chunks per row
#define CHUNKS (SMROWS * NCHUNK)   // 120
#define STAGE_ELEMS (SMROWS * SMSTRIDE)
#define NBUF 6

#define ALPHA_LIF 0.85f
#define V_TH      2.0f
#define ALPHA_LI  0.9f

typedef unsigned long long u64;

// ---- packed f32x2 helpers ----
__device__ __forceinline__ u64 pk(float lo, float hi) {
    u64 r; asm("mov.b64 %0, {%1, %2};" : "=l"(r) : "f"(lo), "f"(hi)); return r;
}
__device__ __forceinline__ void upk(u64 p, float& lo, float& hi) {
    asm("mov.b64 {%0, %1}, %2;" : "=f"(lo), "=f"(hi) : "l"(p));
}
__device__ __forceinline__ void ffma2(u64& acc, u64 a, u64 b) {
    asm("fma.rn.f32x2 %0, %1, %2, %0;" : "+l"(acc) : "l"(a), "l"(b));
}
__device__ __forceinline__ u64 ffma2g(u64 a, u64 b, u64 c) {
    u64 d; asm("fma.rn.f32x2 %0, %1, %2, %3;" : "=l"(d) : "l"(a), "l"(b), "l"(c)); return d;
}

// ---- cp.async helpers ----
__device__ __forceinline__ void cp_async16(float* smem_dst, const float* gsrc, bool pred) {
    uint32_t s = (uint32_t)__cvta_generic_to_shared(smem_dst);
    int srcsz = pred ? 16 : 0;
    asm volatile("cp.async.cg.shared.global [%0], [%1], 16, %2;\n"
                 :: "r"(s), "l"(gsrc), "r"(srcsz));
}
__device__ __forceinline__ void cp_async_commit() {
    asm volatile("cp.async.commit_group;\n" ::: "memory");
}
__device__ __forceinline__ void cp_async_wait2() {
    asm volatile("cp.async.wait_group 2;\n" ::: "memory");
}

// 5x5 conv for 2 output rows x 4 cols from one staged frame.
// Taps f0..f7 at smem cols tx*4+2 .. tx*4+9 of the 40-wide layout
// (three aligned, conflict-free LDS.128 per row).
__device__ __forceinline__ void conv_frame(const float* sbuf, int yA, int tx,
                                           const u64* W2, u64 ZERO2,
                                           u64& Aa0, u64& Aa1, u64& Ab0, u64& Ab1) {
    Aa0 = ZERO2; Aa1 = ZERO2; Ab0 = ZERO2; Ab1 = ZERO2;
#pragma unroll
    for (int r = 0; r < 6; r++) {
        const float* rp = &sbuf[(yA + r) * SMSTRIDE + tx * 4];
        float4 qa = *(const float4*)rp;
        float4 qm = *(const float4*)(rp + 4);
        float4 qb = *(const float4*)(rp + 8);
        u64 AP0 = pk(qa.z, qa.w);   // (f0,f1)
        u64 AP1 = pk(qm.x, qm.y);   // (f2,f3)
        u64 AP2 = pk(qm.z, qm.w);   // (f4,f5)
        u64 AP3 = pk(qb.x, qb.y);   // (f6,f7)
        u64 P12 = pk(qa.w, qm.x);   // (f1,f2)
        u64 P34 = pk(qm.y, qm.z);   // (f3,f4)
        u64 P56 = pk(qm.w, qb.x);   // (f5,f6)

        if (r < 5) {
            ffma2(Aa0, W2[r*5+0], AP0);
            ffma2(Aa0, W2[r*5+1], P12);
            ffma2(Aa0, W2[r*5+2], AP1);
            ffma2(Aa0, W2[r*5+3], P34);
            ffma2(Aa0, W2[r*5+4], AP2);

            ffma2(Aa1, W2[r*5+0], AP1);
            ffma2(Aa1, W2[r*5+1], P34);
            ffma2(Aa1, W2[r*5+2], AP2);
            ffma2(Aa1, W2[r*5+3], P56);
            ffma2(Aa1, W2[r*5+4], AP3);
        }
        if (r >= 1) {
            int q = (r - 1) * 5;
            ffma2(Ab0, W2[q+0], AP0);
            ffma2(Ab0, W2[q+1], P12);
            ffma2(Ab0, W2[q+2], AP1);
            ffma2(Ab0, W2[q+3], P34);
            ffma2(Ab0, W2[q+4], AP2);

            ffma2(Ab1, W2[q+0], AP1);
            ffma2(Ab1, W2[q+1], P34);
            ffma2(Ab1, W2[q+2], AP2);
            ffma2(Ab1, W2[q+3], P56);
            ffma2(Ab1, W2[q+4], AP3);
        }
    }
}

// FastLIF (soft reset) + FastLI for 2 packed col-pairs; stores float4.
__device__ __forceinline__ void lif_update(u64& S1_0, u64& S1_1, u64& S2_0, u64& S2_1,
                                           u64 A0, u64 A1,
                                           u64 ALIF2, u64 NTH2, u64 ALI2,
                                           float* optr) {
    u64 V0 = ffma2g(ALIF2, S1_0, A0);
    u64 V1 = ffma2g(ALIF2, S1_1, A1);
    float v0, v1, v2, v3;
    upk(V0, v0, v1);
    upk(V1, v2, v3);
    float k0 = (v0 >= V_TH) ? 1.0f : 0.0f;
    float k1 = (v1 >= V_TH) ? 1.0f : 0.0f;
    float k2 = (v2 >= V_TH) ? 1.0f : 0.0f;
    float k3 = (v3 >= V_TH) ? 1.0f : 0.0f;
    u64 K0 = pk(k0, k1);
    u64 K1 = pk(k2, k3);
    S1_0 = ffma2g(K0, NTH2, V0);
    S1_1 = ffma2g(K1, NTH2, V1);
    S2_0 = ffma2g(ALI2, S2_0, K0);
    S2_1 = ffma2g(ALI2, S2_1, K1);
    float4 o;
    upk(S2_0, o.x, o.y);
    upk(S2_1, o.z, o.w);
    *(float4*)optr = o;
}

__global__ __launch_bounds__(32)
void snn_fused_kernel(const float* __restrict__ x,
                      const float* __restrict__ kw,
                      float* __restrict__ out) {
    __shared__ float sm[NBUF][STAGE_ELEMS];

    const int tid = threadIdx.x;          // 0..31 (one warp per CTA)
    const int tx  = tid & 7;
    const int ty2 = tid >> 3;
    const int yA  = ty2 * 2;
    const int gx0 = blockIdx.x * TILE_W;
    const int gy0 = blockIdx.y * TILE_H;

    u64 W2[25];
#pragma unroll
    for (int i = 0; i < 25; i++) { float wv = __ldg(&kw[i]); W2[i] = pk(wv, wv); }

    const u64 ALIF2 = pk(ALPHA_LIF, ALPHA_LIF);
    const u64 NTH2  = pk(-V_TH, -V_TH);
    const u64 ALI2  = pk(ALPHA_LI, ALPHA_LI);
    const u64 ZERO2 = pk(0.f, 0.f);

    // Vector staging map: 120 float4 chunks, 4 per thread.
    int  goff[4]; int sdst[4]; bool gok[4]; bool act[4];
#pragma unroll
    for (int j = 0; j < 4; j++) {
        int i = tid + j * 32;
        act[j] = (i < CHUNKS);
        int r = i / NCHUNK;
        int k = i - r * NCHUNK;
        int gy  = gy0 - 2 + r;
        int gxc = gx0 - 4 + 4 * k;
        bool ok = act[j] && ((unsigned)gy < (unsigned)HH) && (gxc >= 0) && (gxc <= WW - 4);
        gok[j]  = ok;
        goff[j] = ok ? (gy * WW + gxc) : 0;
        sdst[j] = r * SMSTRIDE + 4 * k;
    }

    // ---- prologue: stage frames 0..3 into bufs 0..3, one group each ----
#pragma unroll
    for (int f = 0; f < 4; f++) {
        const float* xf = x + f * (HH * WW);
#pragma unroll
        for (int j = 0; j < 4; j++)
            if (act[j]) cp_async16(&sm[f][sdst[j]], &xf[goff[j]], gok[j]);
        cp_async_commit();
    }

    // packed per-pixel LIF / LI state for 2 rows x 4 cols
    u64 S1A0 = ZERO2, S1A1 = ZERO2, S1B0 = ZERO2, S1B1 = ZERO2;
    u64 S2A0 = ZERO2, S2A1 = ZERO2, S2B0 = ZERO2, S2B1 = ZERO2;

    float* ot = out + (gy0 + yA) * WW + gx0 + tx * 4;

    int b0 = 0;   // buffer of frame t; frame t+1 in b0+1 (mod 6)

    for (int t = 0; t < T_STEPS; t += 2) {
        // frames t, t+1 complete (2 newest groups = frames t+2, t+3 may be pending)
        cp_async_wait2();
        __syncwarp();

        // stage frames t+4, t+5 into buffers read 2 iterations ago
        {
            int b4 = b0 + 4; if (b4 >= NBUF) b4 -= NBUF;
            int b5 = b4 + 1; if (b5 >= NBUF) b5 -= NBUF;
            const float* x4 = x + (t + 4) * (HH * WW);
            if (t + 4 < T_STEPS) {
#pragma unroll
                for (int j = 0; j < 4; j++)
                    if (act[j]) cp_async16(&sm[b4][sdst[j]], &x4[goff[j]], gok[j]);
            }
            cp_async_commit();
            if (t + 5 < T_STEPS) {
                const float* x5 = x4 + HH * WW;
#pragma unroll
                for (int j = 0; j < 4; j++)
                    if (act[j]) cp_async16(&sm[b5][sdst[j]], &x5[goff[j]], gok[j]);
            }
            cp_async_commit();
        }

        int b1 = b0 + 1; if (b1 >= NBUF) b1 -= NBUF;

        // two independent convs (8 accumulator chains + 36 LDS in flight)
        u64 Xa0, Xa1, Xb0, Xb1;   // frame t
        u64 Ya0, Ya1, Yb0, Yb1;   // frame t+1
        conv_frame(&sm[b0][0], yA, tx, W2, ZERO2, Xa0, Xa1, Xb0, Xb1);
        conv_frame(&sm[b1][0], yA, tx, W2, ZERO2, Ya0, Ya1, Yb0, Yb1);

        // sequential LIF updates (frame t then t+1), identical order to R12
        lif_update(S1A0, S1A1, S2A0, S2A1, Xa0, Xa1, ALIF2, NTH2, ALI2, ot);
        lif_update(S1B0, S1B1, S2B0, S2B1, Xb0, Xb1, ALIF2, NTH2, ALI2, ot + WW);
        ot += HH * WW;
        lif_update(S1A0, S1A1, S2A0, S2A1, Ya0, Ya1, ALIF2, NTH2, ALI2, ot);
        lif_update(S1B0, S1B1, S2B0, S2B1, Yb0, Yb1, ALIF2, NTH2, ALI2, ot + WW);
        ot += HH * WW;

        b0 += 2; if (b0 >= NBUF) b0 -= NBUF;
    }
}

extern "C" void kernel_launch(void* const* d_in, const int* in_sizes, int n_in,
                              void* d_out, int out_size) {
    const float* x  = (const float*)d_in[0];   // [256,1,512,512] f32
    const float* kw = (const float*)d_in[1];   // [1,1,5,5] f32
    float* out = (float*)d_out;                // [256,1,512,512] f32
    (void)in_sizes; (void)n_in; (void)out_size;

    dim3 grid(WW / TILE_W, HH / TILE_H);       // 16 x 64 = 1024 warp-sized CTAs
    dim3 block(32);
    snn_fused_kernel<<<grid, block>>>(x, kw, out);
}

// round 16
// speedup vs baseline: 1.1305x; 1.0210x over previous
#include <cuda_runtime.h>
#include <cstdint>

#define T_STEPS 256
#define HH 512
#define WW 512
#define FRAME (HH * WW)
#define TILE_W 32
#define TILE_H 8
#define SMROWS 12           // TILE_H + 2*2 halo rows
#define SMSTRIDE 40         // floats per staged row: cols [gx0-4, gx0+36)
#define NCHUNK 10           // float4 chunks per row
#define CHUNKS (SMROWS * NCHUNK)   // 120
#define STAGE_ELEMS (SMROWS * SMSTRIDE)   // 480 floats
#define STAGE_BYTES (STAGE_ELEMS * 4)     // 1920
#define NBUF 8

#define ALPHA_LIF 0.85f
#define V_TH      2.0f
#define ALPHA_LI  0.9f

typedef unsigned long long u64;

// ---- packed f32x2 helpers ----
__device__ __forceinline__ u64 pk(float lo, float hi) {
    u64 r; asm("mov.b64 %0, {%1, %2};" : "=l"(r) : "f"(lo), "f"(hi)); return r;
}
__device__ __forceinline__ void upk(u64 p, float& lo, float& hi) {
    asm("mov.b64 {%0, %1}, %2;" : "=f"(lo), "=f"(hi) : "l"(p));
}
__device__ __forceinline__ void ffma2(u64& acc, u64 a, u64 b) {
    asm("fma.rn.f32x2 %0, %1, %2, %0;" : "+l"(acc) : "l"(a), "l"(b));
}
__device__ __forceinline__ u64 ffma2g(u64 a, u64 b, u64 c) {
    u64 d; asm("fma.rn.f32x2 %0, %1, %2, %3;" : "=l"(d) : "l"(a), "l"(b), "l"(c)); return d;
}

// ---- cp.async helpers (u32 smem address form) ----
__device__ __forceinline__ void cp_async16u(uint32_t saddr, const float* gsrc, bool pred) {
    int srcsz = pred ? 16 : 0;
    asm volatile("cp.async.cg.shared.global [%0], [%1], 16, %2;\n"
                 :: "r"(saddr), "l"(gsrc), "r"(srcsz));
}
__device__ __forceinline__ void cp_async_commit() {
    asm volatile("cp.async.commit_group;\n" ::: "memory");
}
__device__ __forceinline__ void cp_async_wait1() {
    asm volatile("cp.async.wait_group 1;\n" ::: "memory");
}

// 5x5 conv for 2 output rows x 4 cols from one staged frame (taps at cols
// tx*4+2..tx*4+9 of the 40-wide layout; three conflict-free LDS.128 per row).
__device__ __forceinline__ void conv_frame(const float* sbuf, int rowoff,
                                           const u64* W2, u64 ZERO2,
                                           u64& Aa0, u64& Aa1, u64& Ab0, u64& Ab1) {
    Aa0 = ZERO2; Aa1 = ZERO2; Ab0 = ZERO2; Ab1 = ZERO2;
#pragma unroll
    for (int r = 0; r < 6; r++) {
        const float* rp = sbuf + rowoff + r * SMSTRIDE;
        float4 qa = *(const float4*)rp;
        float4 qm = *(const float4*)(rp + 4);
        float4 qb = *(const float4*)(rp + 8);
        u64 AP0 = pk(qa.z, qa.w);   // (f0,f1)
        u64 AP1 = pk(qm.x, qm.y);   // (f2,f3)
        u64 AP2 = pk(qm.z, qm.w);   // (f4,f5)
        u64 AP3 = pk(qb.x, qb.y);   // (f6,f7)
        u64 P12 = pk(qa.w, qm.x);   // (f1,f2)
        u64 P34 = pk(qm.y, qm.z);   // (f3,f4)
        u64 P56 = pk(qm.w, qb.x);   // (f5,f6)

        if (r < 5) {
            ffma2(Aa0, W2[r*5+0], AP0);
            ffma2(Aa0, W2[r*5+1], P12);
            ffma2(Aa0, W2[r*5+2], AP1);
            ffma2(Aa0, W2[r*5+3], P34);
            ffma2(Aa0, W2[r*5+4], AP2);

            ffma2(Aa1, W2[r*5+0], AP1);
            ffma2(Aa1, W2[r*5+1], P34);
            ffma2(Aa1, W2[r*5+2], AP2);
            ffma2(Aa1, W2[r*5+3], P56);
            ffma2(Aa1, W2[r*5+4], AP3);
        }
        if (r >= 1) {
            int q = (r - 1) * 5;
            ffma2(Ab0, W2[q+0], AP0);
            ffma2(Ab0, W2[q+1], P12);
            ffma2(Ab0, W2[q+2], AP1);
            ffma2(Ab0, W2[q+3], P34);
            ffma2(Ab0, W2[q+4], AP2);

            ffma2(Ab1, W2[q+0], AP1);
            ffma2(Ab1, W2[q+1], P34);
            ffma2(Ab1, W2[q+2], AP2);
            ffma2(Ab1, W2[q+3], P56);
            ffma2(Ab1, W2[q+4], AP3);
        }
    }
}

// FastLIF (soft reset) + FastLI for 2 packed col-pairs; stores float4.
__device__ __forceinline__ void lif_update(u64& S1_0, u64& S1_1, u64& S2_0, u64& S2_1,
                                           u64 A0, u64 A1,
                                           u64 ALIF2, u64 NTH2, u64 ALI2,
                                           float* optr) {
    u64 V0 = ffma2g(ALIF2, S1_0, A0);
    u64 V1 = ffma2g(ALIF2, S1_1, A1);
    float v0, v1, v2, v3;
    upk(V0, v0, v1);
    upk(V1, v2, v3);
    float k0 = (v0 >= V_TH) ? 1.0f : 0.0f;
    float k1 = (v1 >= V_TH) ? 1.0f : 0.0f;
    float k2 = (v2 >= V_TH) ? 1.0f : 0.0f;
    float k3 = (v3 >= V_TH) ? 1.0f : 0.0f;
    u64 K0 = pk(k0, k1);
    u64 K1 = pk(k2, k3);
    S1_0 = ffma2g(K0, NTH2, V0);
    S1_1 = ffma2g(K1, NTH2, V1);
    S2_0 = ffma2g(ALI2, S2_0, K0);
    S2_1 = ffma2g(ALI2, S2_1, K1);
    float4 o;
    upk(S2_0, o.x, o.y);
    upk(S2_1, o.z, o.w);
    *(float4*)optr = o;
}

// One 2-frame chunk. B0/B1/B4/B5 are COMPILE-TIME buffer indices.
// Staged pair (FT+4, FT+5) shares one commit group; wait_group 1 at the top
// guarantees group (FT, FT+1) is complete (only (FT+2, FT+3) stays in flight).
#define TIME_CHUNK(B0, B1, B4, B5, FT)                                        \
    {                                                                         \
        cp_async_wait1();                                                     \
        __syncwarp();                                                         \
        if ((FT) + 4 < T_STEPS) {                                             \
            const float* x4 = x + (size_t)((FT) + 4) * FRAME;                 \
            _Pragma("unroll")                                                 \
            for (int j = 0; j < 4; j++)                                       \
                if (act[j]) cp_async16u(sa[j] + (B4) * STAGE_BYTES,           \
                                        &x4[goff[j]], gok[j]);                \
            if ((FT) + 5 < T_STEPS) {                                         \
                const float* x5 = x4 + FRAME;                                 \
                _Pragma("unroll")                                             \
                for (int j = 0; j < 4; j++)                                   \
                    if (act[j]) cp_async16u(sa[j] + (B5) * STAGE_BYTES,       \
                                            &x5[goff[j]], gok[j]);            \
            }                                                                 \
        }                                                                     \
        cp_async_commit();                                                    \
        u64 Xa0, Xa1, Xb0, Xb1, Ya0, Ya1, Yb0, Yb1;                           \
        conv_frame(&sm[B0][0], rowoff, W2, ZERO2, Xa0, Xa1, Xb0, Xb1);        \
        conv_frame(&sm[B1][0], rowoff, W2, ZERO2, Ya0, Ya1, Yb0, Yb1);        \
        lif_update(S1A0, S1A1, S2A0, S2A1, Xa0, Xa1, ALIF2, NTH2, ALI2, ot);  \
        lif_update(S1B0, S1B1, S2B0, S2B1, Xb0, Xb1, ALIF2, NTH2, ALI2, ot + WW); \
        ot += FRAME;                                                          \
        lif_update(S1A0, S1A1, S2A0, S2A1, Ya0, Ya1, ALIF2, NTH2, ALI2, ot);  \
        lif_update(S1B0, S1B1, S2B0, S2B1, Yb0, Yb1, ALIF2, NTH2, ALI2, ot + WW); \
        ot += FRAME;                                                          \
    }

__global__ __launch_bounds__(32)
void snn_fused_kernel(const float* __restrict__ x,
                      const float* __restrict__ kw,
                      float* __restrict__ out) {
    __shared__ float sm[NBUF][STAGE_ELEMS];   // 15360 B

    const int tid = threadIdx.x;          // 0..31 (one warp per CTA)
    const int tx  = tid & 7;
    const int ty2 = tid >> 3;
    const int yA  = ty2 * 2;
    const int gx0 = blockIdx.x * TILE_W;
    const int gy0 = blockIdx.y * TILE_H;
    const int rowoff = yA * SMSTRIDE + tx * 4;

    u64 W2[25];
#pragma unroll
    for (int i = 0; i < 25; i++) { float wv = __ldg(&kw[i]); W2[i] = pk(wv, wv); }

    const u64 ALIF2 = pk(ALPHA_LIF, ALPHA_LIF);
    const u64 NTH2  = pk(-V_TH, -V_TH);
    const u64 ALI2  = pk(ALPHA_LI, ALPHA_LI);
    const u64 ZERO2 = pk(0.f, 0.f);

    // Vector staging map: 120 float4 chunks, 4 per thread.
    int  goff[4]; bool gok[4]; bool act[4];
    uint32_t sa[4];   // smem byte address in buffer 0 for this thread's chunk j
#pragma unroll
    for (int j = 0; j < 4; j++) {
        int i = tid + j * 32;
        act[j] = (i < CHUNKS);
        int r = i / NCHUNK;
        int k = i - r * NCHUNK;
        int gy  = gy0 - 2 + r;
        int gxc = gx0 - 4 + 4 * k;
        bool ok = act[j] && ((unsigned)gy < (unsigned)HH) && (gxc >= 0) && (gxc <= WW - 4);
        gok[j]  = ok;
        goff[j] = ok ? (gy * WW + gxc) : 0;
        sa[j]   = (uint32_t)__cvta_generic_to_shared(&sm[0][r * SMSTRIDE + 4 * k]);
    }

    // ---- prologue: stage frames 0..3 as two 2-frame groups ----
#pragma unroll
    for (int g = 0; g < 2; g++) {
#pragma unroll
        for (int f = 0; f < 2; f++) {
            int fr = 2 * g + f;
            const float* xf = x + (size_t)fr * FRAME;
#pragma unroll
            for (int j = 0; j < 4; j++)
                if (act[j]) cp_async16u(sa[j] + fr * STAGE_BYTES, &xf[goff[j]], gok[j]);
        }
        cp_async_commit();
    }

    // packed per-pixel LIF / LI state for 2 rows x 4 cols
    u64 S1A0 = ZERO2, S1A1 = ZERO2, S1B0 = ZERO2, S1B1 = ZERO2;
    u64 S2A0 = ZERO2, S2A1 = ZERO2, S2B0 = ZERO2, S2B1 = ZERO2;

    float* ot = out + (gy0 + yA) * WW + gx0 + tx * 4;

    for (int t = 0; t < T_STEPS; t += 8) {
        TIME_CHUNK(0, 1, 4, 5, t + 0)
        TIME_CHUNK(2, 3, 6, 7, t + 2)
        TIME_CHUNK(4, 5, 0, 1, t + 4)
        TIME_CHUNK(6, 7, 2, 3, t + 6)
    }
}

extern "C" void kernel_launch(void* const* d_in, const int* in_sizes, int n_in,
                              void* d_out, int out_size) {
    const float* x  = (const float*)d_in[0];   // [256,1,512,512] f32
    const float* kw = (const float*)d_in[1];   // [1,1,5,5] f32
    float* out = (float*)d_out;                // [256,1,512,512] f32
    (void)in_sizes; (void)n_in; (void)out_size;

    dim3 grid(WW / TILE_W, HH / TILE_H);       // 16 x 64 = 1024 warp-sized CTAs
    dim3 block(32);
    snn_fused_kernel<<<grid, block>>>(x, kw, out);
}